// round 1
// baseline (speedup 1.0000x reference)
#include <cuda_runtime.h>
#include <math_constants.h>

#define L_LEN  512
#define D_DIM  4096
#define H_NUM  8
#define D_HEAD 512
#define TOPK   12
#define CPB    32          // channels per block
#define PADA   513         // pitch for FFT buffers (odd -> conflict-free transpose)
#define PADB   33          // pitch for V / out tiles

// scratch: per-channel top-k weights + indices (B<=16)
__device__ float g_w[16 * H_NUM * D_HEAD * TOPK];
__device__ int   g_i[16 * H_NUM * D_HEAD * TOPK];

__device__ __forceinline__ int brev9(int x) { return (int)(__brev((unsigned)x) >> 23); }

// ---------------------------------------------------------------------------
// Kernel A: per-channel circular cross-correlation via FFT, top-12 + softmax.
// One warp per channel, 32 channels per 1024-thread block.
// X = q + i*k ; forward radix-2 DIF (bit-reversed out) ; cross-spectrum in
// bit-reversed domain ; inverse (exact stage-inverse of DIF) -> natural order.
// ---------------------------------------------------------------------------
extern "C" __global__ void __launch_bounds__(1024, 1)
corr_topk_kernel(const float* __restrict__ Q, const float* __restrict__ K) {
    extern __shared__ float sm[];
    float* xre = sm;                       // [CPB][PADA]
    float* xim = sm + CPB * PADA;          // [CPB][PADA]
    float* twr = xim + CPB * PADA;         // [256]
    float* twi = twr + 256;                // [256]

    const int tid  = threadIdx.x;
    const int warp = tid >> 5;
    const int lane = tid & 31;
    const int bh   = blockIdx.x;
    const int b    = bh >> 3;
    const int h    = bh & 7;
    const int cbase = blockIdx.y * CPB;

    // twiddle table: tw[x] = exp(-2*pi*i*x/512)
    if (tid < 256) {
        float s, c;
        sincosf(-2.0f * (float)M_PI * (float)tid * (1.0f / 512.0f), &s, &c);
        twr[tid] = c; twi[tid] = s;
    }

    // cooperative coalesced load: Q -> re, K -> im (transposed to channel-major)
    const size_t base = (size_t)b * L_LEN * D_DIM + (size_t)h * D_HEAD + cbase;
    {
        const int c  = tid & 31;
        for (int t = tid >> 5; t < L_LEN; t += 32) {
            size_t g = base + (size_t)t * D_DIM + c;
            xre[c * PADA + t] = Q[g];
            xim[c * PADA + t] = K[g];
        }
    }
    __syncthreads();

    float* re = xre + warp * PADA;
    float* im = xim + warp * PADA;

    // ---- forward DIF FFT (natural in -> bit-reversed out) ----
    for (int s = 8; s >= 0; --s) {
        const int m = 1 << s;
        #pragma unroll
        for (int k = 0; k < 8; ++k) {
            int u  = lane + (k << 5);
            int j  = u & (m - 1);
            int p  = ((u >> s) << (s + 1)) | j;
            int q  = p + m;
            int jt = j << (8 - s);
            float ar = re[p], ai = im[p];
            float br = re[q], bi = im[q];
            float wr = twr[jt], wi = twi[jt];
            re[p] = ar + br;  im[p] = ai + bi;
            float tr = ar - br, ti = ai - bi;
            re[q] = tr * wr - ti * wi;
            im[q] = tr * wi + ti * wr;
        }
        __syncwarp();
    }

    // ---- cross spectrum P[f] = Qf*conj(Kf)/512, in bit-reversed positions ----
    // X[f] = Qf + i*Kf ; conj(X[N-f]) = Qf - i*Kf. Pairs (f, 512-f) disjoint
    // per handler, each position read+written by exactly one lane -> racefree.
    const float inv_n = 1.0f / 512.0f;
    #pragma unroll
    for (int k = 0; k < 8; ++k) {
        int f = 1 + lane + (k << 5);      // f in [1, 256]
        if (f == 256) {
            int pb = brev9(256);
            float qr = re[pb], kr = im[pb];   // both real at Nyquist
            re[pb] = qr * kr * inv_n;
            im[pb] = 0.f;
        } else {
            int p1 = brev9(f);
            int p2 = brev9(512 - f);
            float ar = re[p1], ai = im[p1];
            float br = re[p2], bi = -im[p2];           // conj(X[512-f])
            float qr = 0.5f * (ar + br), qi = 0.5f * (ai + bi);
            float dr = ar - br,          di = ai - bi;
            float kr = 0.5f * di,        ki = -0.5f * dr;   // (A-B)/(2i)
            float pr = (qr * kr + qi * ki) * inv_n;
            float pi = (qi * kr - qr * ki) * inv_n;
            re[p1] = pr;  im[p1] = pi;
            re[p2] = pr;  im[p2] = -pi;                // Hermitian partner
        }
    }
    if (lane == 0) {               // f = 0 (DC), both real
        float v = re[0] * im[0] * inv_n;
        re[0] = v; im[0] = 0.f;
    }
    __syncwarp();

    // ---- inverse: exact stage-inverse of DIF (conj twiddles), the nine 1/2
    // factors were folded into inv_n above. bit-reversed in -> natural out. ----
    for (int s = 0; s <= 8; ++s) {
        const int m = 1 << s;
        #pragma unroll
        for (int k = 0; k < 8; ++k) {
            int u  = lane + (k << 5);
            int j  = u & (m - 1);
            int p  = ((u >> s) << (s + 1)) | j;
            int q  = p + m;
            int jt = j << (8 - s);
            float wr = twr[jt], wi = -twi[jt];
            float ar  = re[p], ai  = im[p];
            float br0 = re[q], bi0 = im[q];
            float br = br0 * wr - bi0 * wi;
            float bi = br0 * wi + bi0 * wr;
            re[p] = ar + br;  im[p] = ai + bi;
            re[q] = ar - br;  im[q] = ai - bi;
        }
        __syncwarp();
    }

    // ---- top-12 (iterative warp argmax; corr = re[t]), stash into im[] ----
    #pragma unroll
    for (int it = 0; it < TOPK; ++it) {
        float lv = -CUDART_INF_F; int li = 0;
        #pragma unroll
        for (int r = 0; r < 16; ++r) {
            int t = lane + (r << 5);           // stride-32 scan: conflict-free
            float v = re[t];
            if (v > lv) { lv = v; li = t; }
        }
        #pragma unroll
        for (int off = 16; off; off >>= 1) {
            float ov = __shfl_xor_sync(0xffffffffu, lv, off);
            int   oi = __shfl_xor_sync(0xffffffffu, li, off);
            if (ov > lv || (ov == lv && oi < li)) { lv = ov; li = oi; }
        }
        if (lane == 0) { im[it] = lv; im[32 + it] = __int_as_float(li); }
        if ((li & 31) == lane) re[li] = -CUDART_INF_F;
        __syncwarp();
    }
    __syncwarp();

    // ---- softmax over the 12 selected values, write w/idx ----
    float mx = im[0];                          // first selected == max
    float ev = (lane < TOPK) ? __expf(im[lane] - mx) : 0.f;
    float ssum = ev;
    #pragma unroll
    for (int off = 16; off; off >>= 1)
        ssum += __shfl_xor_sync(0xffffffffu, ssum, off);

    if (lane < TOPK) {
        int ch = (bh * D_HEAD + cbase + warp) * TOPK;
        g_w[ch + lane] = ev / ssum;
        g_i[ch + lane] = __float_as_int(im[32 + lane]);
    }
}

// ---------------------------------------------------------------------------
// Kernel B: out[b,l,h*512+c] = sum_i w_i * V[b, min(idx_i+l, 511), h*512+c]
// Stage V tile in SMEM; warp-per-channel, lane-per-l -> conflict-free gather;
// accumulate into SMEM out tile, then coalesced store.
// ---------------------------------------------------------------------------
extern "C" __global__ void __launch_bounds__(1024, 1)
gather_out_kernel(const float* __restrict__ V, float* __restrict__ out) {
    extern __shared__ float sm[];
    float* vs = sm;                      // [512][PADB]
    float* os = sm + L_LEN * PADB;       // [512][PADB]

    const int tid  = threadIdx.x;
    const int warp = tid >> 5;
    const int lane = tid & 31;
    const int bh   = blockIdx.x;
    const int b    = bh >> 3;
    const int h    = bh & 7;
    const int cbase = blockIdx.y * CPB;

    const size_t base = (size_t)b * L_LEN * D_DIM + (size_t)h * D_HEAD + cbase;

    // coalesced V tile load
    {
        const int c = tid & 31;
        for (int t = tid >> 5; t < L_LEN; t += 32)
            vs[t * PADB + c] = V[base + (size_t)t * D_DIM + c];
    }
    __syncthreads();

    // this warp's channel = cbase + warp; broadcast w/idx loads
    const int ch = (bh * D_HEAD + cbase + warp) * TOPK;
    float w[TOPK]; int ix[TOPK];
    #pragma unroll
    for (int i = 0; i < TOPK; ++i) { w[i] = g_w[ch + i]; ix[i] = g_i[ch + i]; }

    #pragma unroll
    for (int p = 0; p < 16; ++p) {
        int l = lane + (p << 5);
        float acc = 0.f;
        #pragma unroll
        for (int i = 0; i < TOPK; ++i) {
            int row = ix[i] + l;
            row = row > 511 ? 511 : row;
            acc += w[i] * vs[row * PADB + warp];   // lanes -> consecutive rows
        }
        os[l * PADB + warp] = acc;
    }
    __syncthreads();

    // coalesced store
    {
        const int c = tid & 31;
        for (int t = tid >> 5; t < L_LEN; t += 32)
            out[base + (size_t)t * D_DIM + c] = os[t * PADB + c];
    }
}

// ---------------------------------------------------------------------------
extern "C" void kernel_launch(void* const* d_in, const int* in_sizes, int n_in,
                              void* d_out, int out_size) {
    (void)n_in; (void)out_size;
    const float* Q = (const float*)d_in[0];
    const float* K = (const float*)d_in[1];
    const float* V = (const float*)d_in[2];
    float* out = (float*)d_out;

    const int B = in_sizes[0] / (L_LEN * D_DIM);   // 16

    const int SMEM_A = (2 * CPB * PADA + 512) * (int)sizeof(float);   // ~133.4 KB
    const int SMEM_B = (2 * L_LEN * PADB) * (int)sizeof(float);       // ~135.2 KB

    cudaFuncSetAttribute(corr_topk_kernel,
                         cudaFuncAttributeMaxDynamicSharedMemorySize, SMEM_A);
    cudaFuncSetAttribute(gather_out_kernel,
                         cudaFuncAttributeMaxDynamicSharedMemorySize, SMEM_B);

    dim3 grid(B * H_NUM, D_HEAD / CPB);   // (128, 16)
    corr_topk_kernel<<<grid, 1024, SMEM_A>>>(Q, K);
    gather_out_kernel<<<grid, 1024, SMEM_B>>>(V, out);
}

// round 2
// speedup vs baseline: 2.0332x; 2.0332x over previous
#include <cuda_runtime.h>
#include <math_constants.h>

#define L_LEN  512
#define D_DIM  4096
#define H_NUM  8
#define D_HEAD 512
#define TOPK   12
#define CPA    8           // channels per block (corr kernel)
#define CPG    8           // channels per block (gather kernel)
#define PADA   516         // tile pitch (mult of 4, %32==4 -> conflict-free transpose)
#define PADG   516

// scratch: per-channel top-k weights + indices (B<=16)
__device__ float g_w[16 * H_NUM * D_HEAD * TOPK];
__device__ int   g_i[16 * H_NUM * D_HEAD * TOPK];

__device__ __forceinline__ int brev9(int x) { return (int)(__brev((unsigned)x) >> 23); }

// ---------------------------------------------------------------------------
// Kernel A: register-resident FFT cross-correlation + top-12 + softmax.
// One warp per channel, 8 channels per 256-thread block.
// Layout: natural index u = r*32 + lane, r = register 0..15.
//   forward DIF: stages m>=32 register-local, m<=16 via shfl_xor.
//   cross-spectrum via short SMEM round-trip (bit-reversed pairing).
//   inverse (exact stage-inverse, conj twiddles) -> natural-order corr.
// ---------------------------------------------------------------------------
extern "C" __global__ void __launch_bounds__(256)
corr_topk_kernel(const float* __restrict__ Q, const float* __restrict__ K) {
    __shared__ float xre[CPA * PADA];
    __shared__ float xim[CPA * PADA];
    __shared__ float twr[256];
    __shared__ float twi[256];

    const int tid  = threadIdx.x;
    const int warp = tid >> 5;
    const int lane = tid & 31;
    const int bh   = blockIdx.x;
    const int b    = bh >> 3;
    const int h    = bh & 7;
    const int cbase = blockIdx.y * CPA;

    // twiddle table: tw[x] = exp(-2*pi*i*x/512)
    {
        float s, c;
        sincosf(-2.0f * (float)M_PI * (float)tid * (1.0f / 512.0f), &s, &c);
        twr[tid] = c; twi[tid] = s;
    }

    // cooperative coalesced load, transposed to channel-major tile
    const size_t base = (size_t)b * L_LEN * D_DIM + (size_t)h * D_HEAD + cbase;
    {
        const int c  = tid & 7;
        const int t0 = tid >> 3;
        for (int t = t0; t < L_LEN; t += 32) {
            size_t g = base + (size_t)t * D_DIM + c;
            xre[c * PADA + t] = Q[g];
            xim[c * PADA + t] = K[g];
        }
    }
    __syncthreads();

    float* re = xre + warp * PADA;
    float* im = xim + warp * PADA;

    // load this warp's channel into registers
    float cre[16], cim[16];
    #pragma unroll
    for (int r = 0; r < 16; ++r) {
        cre[r] = re[r * 32 + lane];
        cim[r] = im[r * 32 + lane];
    }
    __syncwarp();

    // ---- forward DIF FFT: register-local stages (m = 256,128,64,32) ----
    #pragma unroll
    for (int s = 8; s >= 5; --s) {
        const int m32 = 1 << (s - 5);
        #pragma unroll
        for (int r = 0; r < 16; ++r) {
            if ((r & m32) == 0) {
                int jt = (((r & (m32 - 1)) << 5) | lane) << (8 - s);
                float wr = twr[jt], wi = twi[jt];
                float ar = cre[r],       ai = cim[r];
                float br = cre[r + m32], bi = cim[r + m32];
                cre[r] = ar + br;  cim[r] = ai + bi;
                float tr = ar - br, ti = ai - bi;
                cre[r + m32] = tr * wr - ti * wi;
                cim[r + m32] = tr * wi + ti * wr;
            }
        }
    }
    // ---- forward DIF: cross-lane stages (m = 16,8,4,2,1) ----
    #pragma unroll
    for (int s = 4; s >= 0; --s) {
        const int m = 1 << s;
        int jt = (lane & (m - 1)) << (8 - s);
        float wr = twr[jt], wi = twi[jt];
        const bool hi = (lane & m) != 0;
        #pragma unroll
        for (int r = 0; r < 16; ++r) {
            float orr = __shfl_xor_sync(0xffffffffu, cre[r], m);
            float oii = __shfl_xor_sync(0xffffffffu, cim[r], m);
            float sr = cre[r] + orr, si = cim[r] + oii;
            float tr = orr - cre[r], ti = oii - cim[r];   // (a - b) on hi lanes
            float pr = tr * wr - ti * wi;
            float pi = tr * wi + ti * wr;
            cre[r] = hi ? pr : sr;
            cim[r] = hi ? pi : si;
        }
    }

    // ---- spill to SMEM for bit-reversed Hermitian cross-spectrum pairing ----
    #pragma unroll
    for (int r = 0; r < 16; ++r) {
        re[r * 32 + lane] = cre[r];
        im[r * 32 + lane] = cim[r];
    }
    __syncwarp();

    const float inv_n = 1.0f / 512.0f;
    #pragma unroll
    for (int k = 0; k < 8; ++k) {
        int f = 1 + lane + (k << 5);      // f in [1, 256]
        if (f == 256) {
            int pb = brev9(256);
            float qr = re[pb], kr = im[pb];   // both real at Nyquist
            re[pb] = qr * kr * inv_n;
            im[pb] = 0.f;
        } else {
            int p1 = brev9(f);
            int p2 = brev9(512 - f);
            float ar = re[p1], ai = im[p1];
            float br = re[p2], bi = -im[p2];             // conj(X[512-f])
            float qr = 0.5f * (ar + br), qi = 0.5f * (ai + bi);
            float dr = ar - br,          di = ai - bi;
            float kr = 0.5f * di,        ki = -0.5f * dr; // (A-B)/(2i)
            float pr = (qr * kr + qi * ki) * inv_n;
            float pi = (qi * kr - qr * ki) * inv_n;
            re[p1] = pr;  im[p1] = pi;
            re[p2] = pr;  im[p2] = -pi;                  // Hermitian partner
        }
    }
    if (lane == 0) {                   // f = 0 (DC), both real
        float v = re[0] * im[0] * inv_n;
        re[0] = v; im[0] = 0.f;
    }
    __syncwarp();

    #pragma unroll
    for (int r = 0; r < 16; ++r) {
        cre[r] = re[r * 32 + lane];
        cim[r] = im[r * 32 + lane];
    }
    __syncwarp();

    // ---- inverse: cross-lane stages (m = 1,2,4,8,16), conj twiddles ----
    #pragma unroll
    for (int s = 0; s <= 4; ++s) {
        const int m = 1 << s;
        int jt = (lane & (m - 1)) << (8 - s);
        float wr = twr[jt], wi = -twi[jt];
        const bool hi = (lane & m) != 0;
        #pragma unroll
        for (int r = 0; r < 16; ++r) {
            // hi lanes pre-rotate their value (b * conj(w))
            float rr = cre[r] * wr - cim[r] * wi;
            float ri = cre[r] * wi + cim[r] * wr;
            float vr = hi ? rr : cre[r];
            float vi = hi ? ri : cim[r];
            float orr = __shfl_xor_sync(0xffffffffu, vr, m);
            float oii = __shfl_xor_sync(0xffffffffu, vi, m);
            cre[r] = hi ? (orr - vr) : (vr + orr);
            cim[r] = hi ? (oii - vi) : (vi + oii);
        }
    }
    // ---- inverse: register-local stages (m = 32,64,128,256) ----
    #pragma unroll
    for (int s = 5; s <= 8; ++s) {
        const int m32 = 1 << (s - 5);
        #pragma unroll
        for (int r = 0; r < 16; ++r) {
            if ((r & m32) == 0) {
                int jt = (((r & (m32 - 1)) << 5) | lane) << (8 - s);
                float wr = twr[jt], wi = -twi[jt];
                float br0 = cre[r + m32], bi0 = cim[r + m32];
                float br = br0 * wr - bi0 * wi;
                float bi = br0 * wi + bi0 * wr;
                float ar = cre[r], ai = cim[r];
                cre[r] = ar + br;        cim[r] = ai + bi;
                cre[r + m32] = ar - br;  cim[r + m32] = ai - bi;
            }
        }
    }

    // ---- corr (real part, natural order) back to SMEM row for top-k ----
    #pragma unroll
    for (int r = 0; r < 16; ++r)
        re[r * 32 + lane] = cre[r];
    __syncwarp();

    // ---- top-12 iterative warp argmax; stash into im[] ----
    #pragma unroll
    for (int it = 0; it < TOPK; ++it) {
        float lv = -CUDART_INF_F; int li = 0;
        #pragma unroll
        for (int r = 0; r < 16; ++r) {
            int t = lane + (r << 5);
            float v = re[t];
            if (v > lv) { lv = v; li = t; }
        }
        #pragma unroll
        for (int off = 16; off; off >>= 1) {
            float ov = __shfl_xor_sync(0xffffffffu, lv, off);
            int   oi = __shfl_xor_sync(0xffffffffu, li, off);
            if (ov > lv || (ov == lv && oi < li)) { lv = ov; li = oi; }
        }
        if (lane == 0) { im[it] = lv; im[32 + it] = __int_as_float(li); }
        if ((li & 31) == lane) re[li] = -CUDART_INF_F;
        __syncwarp();
    }
    __syncwarp();

    // ---- softmax over the 12 selected values ----
    float mx = im[0];                          // first selected == max
    float ev = (lane < TOPK) ? __expf(im[lane] - mx) : 0.f;
    float ssum = ev;
    #pragma unroll
    for (int off = 16; off; off >>= 1)
        ssum += __shfl_xor_sync(0xffffffffu, ssum, off);

    if (lane < TOPK) {
        int ch = (bh * D_HEAD + cbase + warp) * TOPK;
        g_w[ch + lane] = ev / ssum;
        g_i[ch + lane] = __float_as_int(im[32 + lane]);
    }
}

// ---------------------------------------------------------------------------
// Kernel B: out[b,l,h*512+c] = sum_i w_i * V[b, min(idx_i+l, 511), h*512+c]
// 8 channels / 256 threads per block -> 33KB smem -> 6 CTAs/SM so the
// load / gather / store phases of different CTAs overlap.
// ---------------------------------------------------------------------------
extern "C" __global__ void __launch_bounds__(256)
gather_out_kernel(const float* __restrict__ V, float* __restrict__ out) {
    __shared__ float vs[CPG * PADG];    // channel-major
    __shared__ float os[CPG * PADG];

    const int tid  = threadIdx.x;
    const int warp = tid >> 5;
    const int lane = tid & 31;
    const int bh   = blockIdx.x;
    const int b    = bh >> 3;
    const int h    = bh & 7;
    const int cbase = blockIdx.y * CPG;

    const size_t base = (size_t)b * L_LEN * D_DIM + (size_t)h * D_HEAD + cbase;

    // coalesced V tile load, transposed to channel-major
    {
        const int c  = tid & 7;
        const int t0 = tid >> 3;
        for (int t = t0; t < L_LEN; t += 32)
            vs[c * PADG + t] = V[base + (size_t)t * D_DIM + c];
    }
    __syncthreads();

    // this warp's channel; broadcast w/idx loads
    const int ch = (bh * D_HEAD + cbase + warp) * TOPK;
    float w[TOPK]; int ix[TOPK];
    #pragma unroll
    for (int i = 0; i < TOPK; ++i) { w[i] = g_w[ch + i]; ix[i] = g_i[ch + i]; }

    const float* vrow = vs + warp * PADG;
    float*       orow = os + warp * PADG;

    #pragma unroll
    for (int p = 0; p < 16; ++p) {
        int l = lane + (p << 5);
        float acc = 0.f;
        #pragma unroll
        for (int i = 0; i < TOPK; ++i) {
            int row = ix[i] + l;
            row = row > 511 ? 511 : row;
            acc += w[i] * vrow[row];          // lanes -> consecutive words
        }
        orow[l] = acc;
    }
    __syncthreads();

    // coalesced transposed store
    {
        const int c  = tid & 7;
        const int t0 = tid >> 3;
        for (int t = t0; t < L_LEN; t += 32)
            out[base + (size_t)t * D_DIM + c] = os[c * PADG + t];
    }
}

// ---------------------------------------------------------------------------
extern "C" void kernel_launch(void* const* d_in, const int* in_sizes, int n_in,
                              void* d_out, int out_size) {
    (void)n_in; (void)out_size;
    const float* Q = (const float*)d_in[0];
    const float* K = (const float*)d_in[1];
    const float* V = (const float*)d_in[2];
    float* out = (float*)d_out;

    const int B = in_sizes[0] / (L_LEN * D_DIM);   // 16

    dim3 grid_a(B * H_NUM, D_HEAD / CPA);   // (128, 64)
    dim3 grid_g(B * H_NUM, D_HEAD / CPG);   // (128, 64)
    corr_topk_kernel<<<grid_a, 256>>>(Q, K);
    gather_out_kernel<<<grid_g, 256>>>(V, out);
}

// round 3
// speedup vs baseline: 3.2411x; 1.5941x over previous
#include <cuda_runtime.h>
#include <math_constants.h>

#define L_LEN  512
#define D_DIM  4096
#define TOPK   12
#define CPA    8           // channels per block
#define PADA   516         // row pitch (mult of 4, %32==4 -> conflict-free coop transpose)

__device__ __forceinline__ int brev9(int x) { return (int)(__brev((unsigned)x) >> 23); }
// XOR swizzle: conflict-free for both {r*32+lane} and {lane*16+r} warp patterns
__device__ __forceinline__ int swz(int u)   { return u ^ (u >> 5); }

// ---------------------------------------------------------------------------
// Fused kernel: per-channel FFT cross-correlation -> top-12 + softmax ->
// weighted delay-gather of V. One warp per channel, 8 channels / 256 threads.
//
// FFT layouts:  A: natural u = r*32 + lane   (stages m=256..32 register-local)
//               B: natural u = lane*16 + r   (stages m=8..1   register-local)
// One shuffle stage (m=16) bridges; swizzled SMEM transposes switch layouts.
// ---------------------------------------------------------------------------
extern "C" __global__ void __launch_bounds__(256)
fused_autocorr_kernel(const float* __restrict__ Q, const float* __restrict__ K,
                      const float* __restrict__ V, float* __restrict__ out) {
    extern __shared__ float smbuf[];
    float* xre = smbuf;                    // [CPA][PADA]  FFT re / later out tile
    float* xim = xre + CPA * PADA;         // [CPA][PADA]  FFT im
    float* vsm = xim + CPA * PADA;         // [CPA][PADA]  V tile (channel-major)
    float* twr = vsm + CPA * PADA;         // [256]
    float* twi = twr + 256;                // [256]

    const int tid  = threadIdx.x;
    const int warp = tid >> 5;
    const int lane = tid & 31;
    const int bh   = blockIdx.x;
    const int b    = bh >> 3;
    const int h    = bh & 7;
    const int cbase = blockIdx.y * CPA;

    // twiddles: tw[x] = exp(-2*pi*i*x/512)
    {
        float s, c;
        sincosf(-2.0f * (float)M_PI * (float)tid * (1.0f / 512.0f), &s, &c);
        twr[tid] = c; twi[tid] = s;
    }

    // cooperative coalesced loads, transposed to channel-major tiles
    const size_t base = (size_t)b * L_LEN * D_DIM + (size_t)h * 512 + cbase;
    {
        const int c  = tid & 7;
        const int t0 = tid >> 3;
        for (int t = t0; t < L_LEN; t += 32) {
            size_t g = base + (size_t)t * D_DIM + c;
            xre[c * PADA + t] = Q[g];
            xim[c * PADA + t] = K[g];
            vsm[c * PADA + t] = V[g];
        }
    }
    __syncthreads();

    float* re = xre + warp * PADA;
    float* im = xim + warp * PADA;

    // load channel into registers, layout A
    float cre[16], cim[16];
    #pragma unroll
    for (int r = 0; r < 16; ++r) {
        cre[r] = re[r * 32 + lane];
        cim[r] = im[r * 32 + lane];
    }
    __syncwarp();

    // ---- forward DIF: register-local stages m = 256,128,64,32 (layout A) ----
    #pragma unroll
    for (int s = 8; s >= 5; --s) {
        const int m32 = 1 << (s - 5);
        #pragma unroll
        for (int r = 0; r < 16; ++r) {
            if ((r & m32) == 0) {
                int jt = (((r & (m32 - 1)) << 5) | lane) << (8 - s);
                float wr = twr[jt], wi = twi[jt];
                float ar = cre[r],       ai = cim[r];
                float br = cre[r + m32], bi = cim[r + m32];
                cre[r] = ar + br;  cim[r] = ai + bi;
                float tr = ar - br, ti = ai - bi;
                cre[r + m32] = tr * wr - ti * wi;
                cim[r + m32] = tr * wi + ti * wr;
            }
        }
    }
    // ---- forward DIF: single shuffle stage m = 16 ----
    {
        int jt = (lane & 15) << 4;
        float wr = twr[jt], wi = twi[jt];
        const bool hi = (lane & 16) != 0;
        #pragma unroll
        for (int r = 0; r < 16; ++r) {
            float orr = __shfl_xor_sync(0xffffffffu, cre[r], 16);
            float oii = __shfl_xor_sync(0xffffffffu, cim[r], 16);
            float sr = cre[r] + orr, si = cim[r] + oii;
            float tr = orr - cre[r], ti = oii - cim[r];    // (a-b) on hi lanes
            float pr = tr * wr - ti * wi;
            float pi = tr * wi + ti * wr;
            cre[r] = hi ? pr : sr;
            cim[r] = hi ? pi : si;
        }
    }
    // ---- transpose A -> B through swizzled SMEM ----
    #pragma unroll
    for (int r = 0; r < 16; ++r) {
        int v = swz(r * 32 + lane);
        re[v] = cre[r];  im[v] = cim[r];
    }
    __syncwarp();
    #pragma unroll
    for (int r = 0; r < 16; ++r) {
        int v = swz(lane * 16 + r);
        cre[r] = re[v];  cim[r] = im[v];
    }
    __syncwarp();
    // ---- forward DIF: register-local stages m = 8,4,2,1 (layout B) ----
    #pragma unroll
    for (int s = 3; s >= 0; --s) {
        const int mm = 1 << s;
        #pragma unroll
        for (int r = 0; r < 16; ++r) {
            if ((r & mm) == 0) {
                int jt = (r & (mm - 1)) << (8 - s);
                float wr = twr[jt], wi = twi[jt];
                float ar = cre[r],      ai = cim[r];
                float br = cre[r + mm], bi = cim[r + mm];
                cre[r] = ar + br;  cim[r] = ai + bi;
                float tr = ar - br, ti = ai - bi;
                cre[r + mm] = tr * wr - ti * wi;
                cim[r + mm] = tr * wi + ti * wr;
            }
        }
    }

    // ---- spill (layout B) for bit-reversed Hermitian cross-spectrum ----
    #pragma unroll
    for (int r = 0; r < 16; ++r) {
        int v = swz(lane * 16 + r);
        re[v] = cre[r];  im[v] = cim[r];
    }
    __syncwarp();

    const float inv_n = 1.0f / 512.0f;
    #pragma unroll
    for (int k = 0; k < 8; ++k) {
        int f = 1 + lane + (k << 5);          // f in [1, 256]
        if (f == 256) {
            int pb = swz(brev9(256));
            float qr = re[pb], kr = im[pb];   // both real at Nyquist
            re[pb] = qr * kr * inv_n;
            im[pb] = 0.f;
        } else {
            int p1 = swz(brev9(f));
            int p2 = swz(brev9(512 - f));
            float ar = re[p1], ai = im[p1];
            float br = re[p2], bi = -im[p2];              // conj(X[512-f])
            float qr = 0.5f * (ar + br), qi = 0.5f * (ai + bi);
            float dr = ar - br,          di = ai - bi;
            float kr = 0.5f * di,        ki = -0.5f * dr;  // (A-B)/(2i)
            float pr = (qr * kr + qi * ki) * inv_n;
            float pi = (qi * kr - qr * ki) * inv_n;
            re[p1] = pr;  im[p1] = pi;
            re[p2] = pr;  im[p2] = -pi;                    // Hermitian partner
        }
    }
    if (lane == 0) {                          // f = 0 (DC), both real
        float v = re[0] * im[0] * inv_n;
        re[0] = v; im[0] = 0.f;
    }
    __syncwarp();

    #pragma unroll
    for (int r = 0; r < 16; ++r) {
        int v = swz(lane * 16 + r);
        cre[r] = re[v];  cim[r] = im[v];
    }
    __syncwarp();

    // ---- inverse: register-local stages m = 1,2,4,8 (layout B, conj tw) ----
    #pragma unroll
    for (int s = 0; s <= 3; ++s) {
        const int mm = 1 << s;
        #pragma unroll
        for (int r = 0; r < 16; ++r) {
            if ((r & mm) == 0) {
                int jt = (r & (mm - 1)) << (8 - s);
                float wr = twr[jt], wi = -twi[jt];
                float b0r = cre[r + mm], b0i = cim[r + mm];
                float br = b0r * wr - b0i * wi;
                float bi = b0r * wi + b0i * wr;
                float ar = cre[r], ai = cim[r];
                cre[r] = ar + br;       cim[r] = ai + bi;
                cre[r + mm] = ar - br;  cim[r + mm] = ai - bi;
            }
        }
    }
    // ---- transpose B -> A through swizzled SMEM ----
    #pragma unroll
    for (int r = 0; r < 16; ++r) {
        int v = swz(lane * 16 + r);
        re[v] = cre[r];  im[v] = cim[r];
    }
    __syncwarp();
    #pragma unroll
    for (int r = 0; r < 16; ++r) {
        int v = swz(r * 32 + lane);
        cre[r] = re[v];  cim[r] = im[v];
    }
    __syncwarp();
    // ---- inverse: single shuffle stage m = 16 (conj tw) ----
    {
        int jt = (lane & 15) << 4;
        float wr = twr[jt], wi = -twi[jt];
        const bool hi = (lane & 16) != 0;
        #pragma unroll
        for (int r = 0; r < 16; ++r) {
            float rr = cre[r] * wr - cim[r] * wi;   // hi lanes pre-rotate b*conj(w)
            float ri = cre[r] * wi + cim[r] * wr;
            float vr = hi ? rr : cre[r];
            float vi = hi ? ri : cim[r];
            float orr = __shfl_xor_sync(0xffffffffu, vr, 16);
            float oii = __shfl_xor_sync(0xffffffffu, vi, 16);
            cre[r] = hi ? (orr - vr) : (vr + orr);
            cim[r] = hi ? (oii - vi) : (vi + oii);
        }
    }
    // ---- inverse: register-local stages m = 32..256 (layout A, conj tw) ----
    #pragma unroll
    for (int s = 5; s <= 8; ++s) {
        const int m32 = 1 << (s - 5);
        #pragma unroll
        for (int r = 0; r < 16; ++r) {
            if ((r & m32) == 0) {
                int jt = (((r & (m32 - 1)) << 5) | lane) << (8 - s);
                float wr = twr[jt], wi = -twi[jt];
                float b0r = cre[r + m32], b0i = cim[r + m32];
                float br = b0r * wr - b0i * wi;
                float bi = b0r * wi + b0i * wr;
                float ar = cre[r], ai = cim[r];
                cre[r] = ar + br;        cim[r] = ai + bi;
                cre[r + m32] = ar - br;  cim[r + m32] = ai - bi;
            }
        }
    }
    // corr (natural order) now lives in cre[], index u = r*32 + lane

    // ---- top-12: register argmax, all-lane broadcast via the reduction ----
    float wv[TOPK]; int wx[TOPK];
    #pragma unroll
    for (int it = 0; it < TOPK; ++it) {
        float lv = -CUDART_INF_F; int li = 0;
        #pragma unroll
        for (int r = 0; r < 16; ++r) {
            int t = r * 32 + lane;
            if (cre[r] > lv) { lv = cre[r]; li = t; }
        }
        #pragma unroll
        for (int off = 16; off; off >>= 1) {
            float ov = __shfl_xor_sync(0xffffffffu, lv, off);
            int   oi = __shfl_xor_sync(0xffffffffu, li, off);
            if (ov > lv || (ov == lv && oi < li)) { lv = ov; li = oi; }
        }
        wv[it] = lv; wx[it] = li;
        const int lr = li >> 5, ll = li & 31;
        #pragma unroll
        for (int r = 0; r < 16; ++r)
            if (r == lr && lane == ll) cre[r] = -CUDART_INF_F;
    }

    // ---- softmax over the 12 selected (every lane holds all 12) ----
    {
        float mx = wv[0], ssum = 0.f;
        #pragma unroll
        for (int i = 0; i < TOPK; ++i) { wv[i] = __expf(wv[i] - mx); ssum += wv[i]; }
        float inv = 1.0f / ssum;
        #pragma unroll
        for (int i = 0; i < TOPK; ++i) wv[i] *= inv;
    }

    // ---- gather: out[l] = sum_i w_i * V[min(idx_i + l, 511)] (own channel) ----
    {
        const float* vrow = vsm + warp * PADA;
        float*       orow = xre + warp * PADA;   // xre row is dead -> out tile
        #pragma unroll
        for (int p = 0; p < 16; ++p) {
            int l = lane + (p << 5);
            float acc = 0.f;
            #pragma unroll
            for (int i = 0; i < TOPK; ++i) {
                int row = wx[i] + l;
                row = row > 511 ? 511 : row;
                acc += wv[i] * vrow[row];
            }
            orow[l] = acc;
        }
    }
    __syncthreads();

    // ---- cooperative coalesced transposed store ----
    {
        const int c  = tid & 7;
        const int t0 = tid >> 3;
        for (int t = t0; t < L_LEN; t += 32)
            out[base + (size_t)t * D_DIM + c] = xre[c * PADA + t];
    }
}

// ---------------------------------------------------------------------------
extern "C" void kernel_launch(void* const* d_in, const int* in_sizes, int n_in,
                              void* d_out, int out_size) {
    (void)n_in; (void)out_size;
    const float* Q = (const float*)d_in[0];
    const float* K = (const float*)d_in[1];
    const float* V = (const float*)d_in[2];
    float* out = (float*)d_out;

    const int B = in_sizes[0] / (L_LEN * D_DIM);   // 16

    const int SMEM = (3 * CPA * PADA + 512) * (int)sizeof(float);   // ~51.5 KB
    cudaFuncSetAttribute(fused_autocorr_kernel,
                         cudaFuncAttributeMaxDynamicSharedMemorySize, SMEM);

    dim3 grid(B * 8, 512 / CPA);   // (128, 64)
    fused_autocorr_kernel<<<grid, 256, SMEM>>>(Q, K, V, out);
}

// round 4
// speedup vs baseline: 3.7661x; 1.1620x over previous
#include <cuda_runtime.h>
#include <math_constants.h>

#define L_LEN  512
#define D_DIM  4096
#define TOPK   12
#define CPA    8           // channels per block
#define PADA   516         // row pitch (%32==4 -> conflict-free coop transpose)

__device__ __forceinline__ int brev9(int x) { return (int)(__brev((unsigned)x) >> 23); }
// XOR swizzle: conflict-free for both {r*32+lane} and {lane*16+r} warp patterns
__device__ __forceinline__ int swz(int u)   { return u ^ (u >> 5); }

// 16th roots of unity: C16[j] = exp(-2*pi*i*j/16)
__device__ constexpr float C16R[8] = { 1.0f,  0.92387953251f,  0.70710678119f,  0.38268343236f,
                                       0.0f, -0.38268343236f, -0.70710678119f, -0.92387953251f };
__device__ constexpr float C16I[8] = { 0.0f, -0.38268343236f, -0.70710678119f, -0.92387953251f,
                                      -1.0f, -0.92387953251f, -0.70710678119f, -0.38268343236f };

// DIF butterfly: (a,b) -> (a+b, (a-b)*w)
__device__ __forceinline__ void bf_dif(float& ar, float& ai, float& br, float& bi,
                                       float wr, float wi) {
    float tr = ar - br, ti = ai - bi;
    ar += br; ai += bi;
    br = tr * wr - ti * wi;
    bi = tr * wi + ti * wr;
}
__device__ __forceinline__ void bf_dif1(float& ar, float& ai, float& br, float& bi) {
    float tr = ar - br, ti = ai - bi;
    ar += br; ai += bi; br = tr; bi = ti;
}
__device__ __forceinline__ void bf_difmi(float& ar, float& ai, float& br, float& bi) {
    float tr = ar - br, ti = ai - bi;        // *( -i ): (tr,ti) -> (ti, -tr)
    ar += br; ai += bi; br = ti; bi = -tr;
}
// DIT (inverse) butterfly with conj(w): (a,b) -> (a + b*conj(w), a - b*conj(w))
__device__ __forceinline__ void bf_dit(float& ar, float& ai, float& br, float& bi,
                                       float wr, float wi) {
    float rr = br * wr + bi * wi;
    float ri = bi * wr - br * wi;
    br = ar - rr; bi = ai - ri;
    ar += rr; ai += ri;
}
__device__ __forceinline__ void bf_dit1(float& ar, float& ai, float& br, float& bi) {
    float rr = br, ri = bi;
    br = ar - rr; bi = ai - ri;
    ar += rr; ai += ri;
}
__device__ __forceinline__ void bf_ditmi(float& ar, float& ai, float& br, float& bi) {
    float rr = -bi, ri = br;                 // b * conj(-i) = b * i
    br = ar - rr; bi = ai - ri;
    ar += rr; ai += ri;
}

// ---------------------------------------------------------------------------
// Fused: per-channel FFT cross-correlation -> top-12 + softmax -> gather of V.
// One warp per channel, 8 channels / 256 threads.
//   layout A: u = r*32 + lane (stages m=256..32 register-local)
//   layout B: u = lane*16 + r (stages m=8..1 register-local)
// All twiddles are constants or derived from t1 = w^lane via squaring.
// ---------------------------------------------------------------------------
extern "C" __global__ void __launch_bounds__(256, 4)
fused_autocorr_kernel(const float* __restrict__ Q, const float* __restrict__ K,
                      const float* __restrict__ V, float* __restrict__ out) {
    extern __shared__ float smbuf[];
    float* xre = smbuf;                    // [CPA][PADA]  FFT re / later out tile
    float* xim = xre + CPA * PADA;         // [CPA][PADA]  FFT im
    float* vsm = xim + CPA * PADA;         // [CPA][PADA]  V tile (channel-major)

    const int tid  = threadIdx.x;
    const int warp = tid >> 5;
    const int lane = tid & 31;
    const int bh   = blockIdx.x;
    const int b    = bh >> 3;
    const int h    = bh & 7;
    const int cbase = blockIdx.y * CPA;

    // cooperative float2 coalesced loads, transposed to channel-major tiles
    const size_t base = (size_t)b * L_LEN * D_DIM + (size_t)h * 512 + cbase;
    {
        const int c2 = (tid & 3) << 1;
        const int t0 = tid >> 2;           // 0..63
        for (int t = t0; t < L_LEN; t += 64) {
            size_t g = base + (size_t)t * D_DIM + c2;
            float2 q2 = *(const float2*)(Q + g);
            float2 k2 = *(const float2*)(K + g);
            float2 v2 = *(const float2*)(V + g);
            xre[c2 * PADA + t] = q2.x;  xre[(c2 + 1) * PADA + t] = q2.y;
            xim[c2 * PADA + t] = k2.x;  xim[(c2 + 1) * PADA + t] = k2.y;
            vsm[c2 * PADA + t] = v2.x;  vsm[(c2 + 1) * PADA + t] = v2.y;
        }
    }
    __syncthreads();

    float* re = xre + warp * PADA;
    float* im = xim + warp * PADA;

    // per-lane twiddle bases: t1 = w^lane, w = exp(-2*pi*i/512)
    float t1i, t1r;
    __sincosf((float)lane * -0.01227184630f, &t1i, &t1r);
    float t2r = t1r * t1r - t1i * t1i, t2i = 2.0f * t1r * t1i;
    float t4r = t2r * t2r - t2i * t2i, t4i = 2.0f * t2r * t2i;
    float t8r = t4r * t4r - t4i * t4i, t8i = 2.0f * t4r * t4i;
    // m=16 shuffle-stage twiddle: exp(-2*pi*i*(lane&15)/32)
    float swi, swr;
    __sincosf((float)(lane & 15) * -0.19634954085f, &swi, &swr);

    // load channel into registers, layout A
    float cre[16], cim[16];
    #pragma unroll
    for (int r = 0; r < 16; ++r) {
        cre[r] = re[r * 32 + lane];
        cim[r] = im[r * 32 + lane];
    }
    __syncwarp();

    // ---- forward DIF, layout A ----
    #pragma unroll
    for (int r = 0; r < 8; ++r) {          // s=8, m=256
        float wr = t1r * C16R[r] - t1i * C16I[r];
        float wi = t1r * C16I[r] + t1i * C16R[r];
        bf_dif(cre[r], cim[r], cre[r + 8], cim[r + 8], wr, wi);
    }
    #pragma unroll
    for (int g = 0; g < 2; ++g)            // s=7, m=128
        #pragma unroll
        for (int j = 0; j < 4; ++j) {
            float wr = t2r * C16R[2 * j] - t2i * C16I[2 * j];
            float wi = t2r * C16I[2 * j] + t2i * C16R[2 * j];
            int r = g * 8 + j;
            bf_dif(cre[r], cim[r], cre[r + 4], cim[r + 4], wr, wi);
        }
    #pragma unroll
    for (int g = 0; g < 4; ++g) {          // s=6, m=64
        int r = g * 4;
        bf_dif(cre[r],     cim[r],     cre[r + 2], cim[r + 2], t4r, t4i);
        bf_dif(cre[r + 1], cim[r + 1], cre[r + 3], cim[r + 3], t4i, -t4r);  // *(t4*-i)
    }
    #pragma unroll
    for (int g = 0; g < 8; ++g) {          // s=5, m=32
        int r = g * 2;
        bf_dif(cre[r], cim[r], cre[r + 1], cim[r + 1], t8r, t8i);
    }
    // ---- forward: shuffle stage m=16 ----
    {
        const bool hi = (lane & 16) != 0;
        #pragma unroll
        for (int r = 0; r < 16; ++r) {
            float orr = __shfl_xor_sync(0xffffffffu, cre[r], 16);
            float oii = __shfl_xor_sync(0xffffffffu, cim[r], 16);
            float sr = cre[r] + orr, si = cim[r] + oii;
            float tr = orr - cre[r], ti = oii - cim[r];    // (a-b) on hi lanes
            float pr = tr * swr - ti * swi;
            float pi = tr * swi + ti * swr;
            cre[r] = hi ? pr : sr;
            cim[r] = hi ? pi : si;
        }
    }
    // ---- transpose A -> B through swizzled SMEM ----
    #pragma unroll
    for (int r = 0; r < 16; ++r) {
        int v = swz(r * 32 + lane);
        re[v] = cre[r];  im[v] = cim[r];
    }
    __syncwarp();
    #pragma unroll
    for (int r = 0; r < 16; ++r) {
        int v = swz(lane * 16 + r);
        cre[r] = re[v];  cim[r] = im[v];
    }
    __syncwarp();
    // ---- forward DIF, layout B (all-constant twiddles) ----
    #pragma unroll
    for (int r = 0; r < 8; ++r) {          // s=3, m=8: tw = C16[r]
        if (r == 0)      bf_dif1 (cre[0], cim[0], cre[8],  cim[8]);
        else if (r == 4) bf_difmi(cre[4], cim[4], cre[12], cim[12]);
        else bf_dif(cre[r], cim[r], cre[r + 8], cim[r + 8], C16R[r], C16I[r]);
    }
    #pragma unroll
    for (int g = 0; g < 2; ++g)            // s=2, m=4: tw = C16[2j]
        #pragma unroll
        for (int j = 0; j < 4; ++j) {
            int r = g * 8 + j;
            if (j == 0)      bf_dif1 (cre[r], cim[r], cre[r + 4], cim[r + 4]);
            else if (j == 2) bf_difmi(cre[r], cim[r], cre[r + 4], cim[r + 4]);
            else bf_dif(cre[r], cim[r], cre[r + 4], cim[r + 4], C16R[2 * j], C16I[2 * j]);
        }
    #pragma unroll
    for (int g = 0; g < 4; ++g) {          // s=1, m=2: tw = 1 or -i
        int r = g * 4;
        bf_dif1 (cre[r],     cim[r],     cre[r + 2], cim[r + 2]);
        bf_difmi(cre[r + 1], cim[r + 1], cre[r + 3], cim[r + 3]);
    }
    #pragma unroll
    for (int g = 0; g < 8; ++g)            // s=0, m=1: tw = 1
        bf_dif1(cre[g * 2], cim[g * 2], cre[g * 2 + 1], cim[g * 2 + 1]);

    // ---- spill (layout B) for bit-reversed Hermitian cross-spectrum ----
    #pragma unroll
    for (int r = 0; r < 16; ++r) {
        int v = swz(lane * 16 + r);
        re[v] = cre[r];  im[v] = cim[r];
    }
    __syncwarp();

    const float inv_n = 1.0f / 512.0f;
    #pragma unroll
    for (int k = 0; k < 8; ++k) {
        int f = 1 + lane + (k << 5);          // f in [1, 256]
        if (f == 256) {
            int pb = swz(brev9(256));
            float qr = re[pb], kr = im[pb];   // both real at Nyquist
            re[pb] = qr * kr * inv_n;
            im[pb] = 0.f;
        } else {
            int p1 = swz(brev9(f));
            int p2 = swz(brev9(512 - f));
            float ar = re[p1], ai = im[p1];
            float br = re[p2], bi = -im[p2];              // conj(X[512-f])
            float qr = 0.5f * (ar + br), qi = 0.5f * (ai + bi);
            float dr = ar - br,          di = ai - bi;
            float kr = 0.5f * di,        ki = -0.5f * dr;  // (A-B)/(2i)
            float pr = (qr * kr + qi * ki) * inv_n;
            float pi = (qi * kr - qr * ki) * inv_n;
            re[p1] = pr;  im[p1] = pi;
            re[p2] = pr;  im[p2] = -pi;                    // Hermitian partner
        }
    }
    if (lane == 0) {                          // f = 0 (DC), both real
        float v = re[0] * im[0] * inv_n;
        re[0] = v; im[0] = 0.f;
    }
    __syncwarp();

    #pragma unroll
    for (int r = 0; r < 16; ++r) {
        int v = swz(lane * 16 + r);
        cre[r] = re[v];  cim[r] = im[v];
    }
    __syncwarp();

    // ---- inverse DIT, layout B ----
    #pragma unroll
    for (int g = 0; g < 8; ++g)            // s=0
        bf_dit1(cre[g * 2], cim[g * 2], cre[g * 2 + 1], cim[g * 2 + 1]);
    #pragma unroll
    for (int g = 0; g < 4; ++g) {          // s=1
        int r = g * 4;
        bf_dit1 (cre[r],     cim[r],     cre[r + 2], cim[r + 2]);
        bf_ditmi(cre[r + 1], cim[r + 1], cre[r + 3], cim[r + 3]);
    }
    #pragma unroll
    for (int g = 0; g < 2; ++g)            // s=2
        #pragma unroll
        for (int j = 0; j < 4; ++j) {
            int r = g * 8 + j;
            if (j == 0)      bf_dit1 (cre[r], cim[r], cre[r + 4], cim[r + 4]);
            else if (j == 2) bf_ditmi(cre[r], cim[r], cre[r + 4], cim[r + 4]);
            else bf_dit(cre[r], cim[r], cre[r + 4], cim[r + 4], C16R[2 * j], C16I[2 * j]);
        }
    #pragma unroll
    for (int r = 0; r < 8; ++r) {          // s=3
        if (r == 0)      bf_dit1 (cre[0], cim[0], cre[8],  cim[8]);
        else if (r == 4) bf_ditmi(cre[4], cim[4], cre[12], cim[12]);
        else bf_dit(cre[r], cim[r], cre[r + 8], cim[r + 8], C16R[r], C16I[r]);
    }
    // ---- transpose B -> A through swizzled SMEM ----
    #pragma unroll
    for (int r = 0; r < 16; ++r) {
        int v = swz(lane * 16 + r);
        re[v] = cre[r];  im[v] = cim[r];
    }
    __syncwarp();
    #pragma unroll
    for (int r = 0; r < 16; ++r) {
        int v = swz(r * 32 + lane);
        cre[r] = re[v];  cim[r] = im[v];
    }
    __syncwarp();
    // ---- inverse: shuffle stage m=16 (conj tw) ----
    {
        const float wr = swr, wi = -swi;
        const bool hi = (lane & 16) != 0;
        #pragma unroll
        for (int r = 0; r < 16; ++r) {
            float rr = cre[r] * wr - cim[r] * wi;   // hi lanes pre-rotate b*conj(w)
            float ri = cre[r] * wi + cim[r] * wr;
            float vr = hi ? rr : cre[r];
            float vi = hi ? ri : cim[r];
            float orr = __shfl_xor_sync(0xffffffffu, vr, 16);
            float oii = __shfl_xor_sync(0xffffffffu, vi, 16);
            cre[r] = hi ? (orr - vr) : (vr + orr);
            cim[r] = hi ? (oii - vi) : (vi + oii);
        }
    }
    // ---- inverse DIT, layout A ----
    #pragma unroll
    for (int g = 0; g < 8; ++g) {          // s=5
        int r = g * 2;
        bf_dit(cre[r], cim[r], cre[r + 1], cim[r + 1], t8r, t8i);
    }
    #pragma unroll
    for (int g = 0; g < 4; ++g) {          // s=6
        int r = g * 4;
        bf_dit(cre[r],     cim[r],     cre[r + 2], cim[r + 2], t4r, t4i);
        bf_dit(cre[r + 1], cim[r + 1], cre[r + 3], cim[r + 3], t4i, -t4r);
    }
    #pragma unroll
    for (int g = 0; g < 2; ++g)            // s=7
        #pragma unroll
        for (int j = 0; j < 4; ++j) {
            float wr = t2r * C16R[2 * j] - t2i * C16I[2 * j];
            float wi = t2r * C16I[2 * j] + t2i * C16R[2 * j];
            int r = g * 8 + j;
            bf_dit(cre[r], cim[r], cre[r + 4], cim[r + 4], wr, wi);
        }
    #pragma unroll
    for (int r = 0; r < 8; ++r) {          // s=8
        float wr = t1r * C16R[r] - t1i * C16I[r];
        float wi = t1r * C16I[r] + t1i * C16R[r];
        bf_dit(cre[r], cim[r], cre[r + 8], cim[r + 8], wr, wi);
    }
    // corr (natural order) now in cre[], index u = r*32 + lane

    // ---- top-12: monotonic uint keys + REDUX warp argmax ----
    unsigned key[16];
    #pragma unroll
    for (int r = 0; r < 16; ++r) {
        unsigned u = __float_as_uint(cre[r]);
        key[r] = (u & 0x80000000u) ? ~u : (u | 0x80000000u);
    }
    float wv[TOPK]; int wx[TOPK];
    #pragma unroll
    for (int it = 0; it < TOPK; ++it) {
        // per-lane max (tree)
        unsigned a0 = max(key[0],  key[1]),  a1 = max(key[2],  key[3]);
        unsigned a2 = max(key[4],  key[5]),  a3 = max(key[6],  key[7]);
        unsigned a4 = max(key[8],  key[9]),  a5 = max(key[10], key[11]);
        unsigned a6 = max(key[12], key[13]), a7 = max(key[14], key[15]);
        unsigned b0 = max(a0, a1), b1 = max(a2, a3), b2 = max(a4, a5), b3 = max(a6, a7);
        unsigned lmax = max(max(b0, b1), max(b2, b3));
        unsigned M = __reduce_max_sync(0xffffffffu, lmax);
        unsigned ball = __ballot_sync(0xffffffffu, lmax == M);
        int wl = __ffs((int)ball) - 1;
        bool pm = (lane == wl);
        int wr = 0;
        #pragma unroll
        for (int r = 0; r < 16; ++r) {
            bool p = pm && (key[r] == M);
            if (p) { wr = r; key[r] = 0u; pm = false; }
        }
        wr = __shfl_sync(0xffffffffu, wr, wl);
        unsigned ub = (M & 0x80000000u) ? (M & 0x7fffffffu) : ~M;
        wv[it] = __uint_as_float(ub);
        wx[it] = (wr << 5) | wl;
    }

    // ---- softmax over the 12 selected (every lane holds all 12) ----
    {
        float mx = wv[0], ssum = 0.f;
        #pragma unroll
        for (int i = 0; i < TOPK; ++i) { wv[i] = __expf(wv[i] - mx); ssum += wv[i]; }
        float inv = 1.0f / ssum;
        #pragma unroll
        for (int i = 0; i < TOPK; ++i) wv[i] *= inv;
    }

    // ---- gather: out[l] = sum_i w_i * V[min(idx_i + l, 511)] (own channel) ----
    {
        const float* vrow = vsm + warp * PADA;
        float*       orow = xre + warp * PADA;   // xre row is dead -> out tile
        #pragma unroll
        for (int p = 0; p < 16; ++p) {
            int l = lane + (p << 5);
            float acc = 0.f;
            #pragma unroll
            for (int i = 0; i < TOPK; ++i) {
                int row = wx[i] + l;
                row = row > 511 ? 511 : row;
                acc += wv[i] * vrow[row];
            }
            orow[l] = acc;
        }
    }
    __syncthreads();

    // ---- cooperative coalesced float2 store ----
    {
        const int c2 = (tid & 3) << 1;
        const int t0 = tid >> 2;
        for (int t = t0; t < L_LEN; t += 64) {
            float2 o2;
            o2.x = xre[c2 * PADA + t];
            o2.y = xre[(c2 + 1) * PADA + t];
            *(float2*)(out + base + (size_t)t * D_DIM + c2) = o2;
        }
    }
}

// ---------------------------------------------------------------------------
extern "C" void kernel_launch(void* const* d_in, const int* in_sizes, int n_in,
                              void* d_out, int out_size) {
    (void)n_in; (void)out_size;
    const float* Q = (const float*)d_in[0];
    const float* K = (const float*)d_in[1];
    const float* V = (const float*)d_in[2];
    float* out = (float*)d_out;

    const int B = in_sizes[0] / (L_LEN * D_DIM);   // 16

    const int SMEM = (3 * CPA * PADA) * (int)sizeof(float);   // 49536 B
    cudaFuncSetAttribute(fused_autocorr_kernel,
                         cudaFuncAttributeMaxDynamicSharedMemorySize, SMEM);

    dim3 grid(B * 8, 512 / CPA);   // (128, 64)
    fused_autocorr_kernel<<<grid, 256, SMEM>>>(Q, K, V, out);
}

// round 5
// speedup vs baseline: 4.1385x; 1.0989x over previous
#include <cuda_runtime.h>
#include <math_constants.h>

#define L_LEN  512
#define D_DIM  4096
#define TOPK   12
#define CPA    8           // channels per block
#define PADA   516         // row pitch (%32==4 -> conflict-free coop transpose)

__device__ __forceinline__ int brev9(int x) { return (int)(__brev((unsigned)x) >> 23); }
// XOR swizzle: conflict-free for both {r*32+lane} and {lane*16+r} warp patterns
__device__ __forceinline__ int swz(int u)   { return u ^ (u >> 5); }

// 16th roots of unity: C16[j] = exp(-2*pi*i*j/16)
__device__ constexpr float C16R[8] = { 1.0f,  0.92387953251f,  0.70710678119f,  0.38268343236f,
                                       0.0f, -0.38268343236f, -0.70710678119f, -0.92387953251f };
__device__ constexpr float C16I[8] = { 0.0f, -0.38268343236f, -0.70710678119f, -0.92387953251f,
                                      -1.0f, -0.92387953251f, -0.70710678119f, -0.38268343236f };

// DIF butterfly: (a,b) -> (a+b, (a-b)*w)
__device__ __forceinline__ void bf_dif(float& ar, float& ai, float& br, float& bi,
                                       float wr, float wi) {
    float tr = ar - br, ti = ai - bi;
    ar += br; ai += bi;
    br = tr * wr - ti * wi;
    bi = tr * wi + ti * wr;
}
__device__ __forceinline__ void bf_dif1(float& ar, float& ai, float& br, float& bi) {
    float tr = ar - br, ti = ai - bi;
    ar += br; ai += bi; br = tr; bi = ti;
}
__device__ __forceinline__ void bf_difmi(float& ar, float& ai, float& br, float& bi) {
    float tr = ar - br, ti = ai - bi;        // *( -i ): (tr,ti) -> (ti, -tr)
    ar += br; ai += bi; br = ti; bi = -tr;
}
// DIT (inverse) butterfly with conj(w): (a,b) -> (a + b*conj(w), a - b*conj(w))
__device__ __forceinline__ void bf_dit(float& ar, float& ai, float& br, float& bi,
                                       float wr, float wi) {
    float rr = br * wr + bi * wi;
    float ri = bi * wr - br * wi;
    br = ar - rr; bi = ai - ri;
    ar += rr; ai += ri;
}
__device__ __forceinline__ void bf_dit1(float& ar, float& ai, float& br, float& bi) {
    float rr = br, ri = bi;
    br = ar - rr; bi = ai - ri;
    ar += rr; ai += ri;
}
__device__ __forceinline__ void bf_ditmi(float& ar, float& ai, float& br, float& bi) {
    float rr = -bi, ri = br;                 // b * conj(-i) = b * i
    br = ar - rr; bi = ai - ri;
    ar += rr; ai += ri;
}

// ---------------------------------------------------------------------------
// Fused: per-channel FFT cross-correlation -> top-12 + softmax -> gather of V.
// One warp per channel, 8 channels / 256 threads, 2 smem tiles only:
// V is loaded into the dead xim tile AFTER selection (corr lives in regs).
// ---------------------------------------------------------------------------
extern "C" __global__ void __launch_bounds__(256, 5)
fused_autocorr_kernel(const float* __restrict__ Q, const float* __restrict__ K,
                      const float* __restrict__ V, float* __restrict__ out) {
    extern __shared__ float smbuf[];
    float* xre = smbuf;                    // [CPA][PADA]  FFT re / later out tile
    float* xim = xre + CPA * PADA;         // [CPA][PADA]  FFT im / later V tile

    const int tid  = threadIdx.x;
    const int warp = tid >> 5;
    const int lane = tid & 31;
    const int bh   = blockIdx.x;
    const int b    = bh >> 3;
    const int h    = bh & 7;
    const int cbase = blockIdx.y * CPA;

    // cooperative float2 coalesced loads (Q,K only), transposed channel-major
    const size_t base = (size_t)b * L_LEN * D_DIM + (size_t)h * 512 + cbase;
    const int c2 = (tid & 3) << 1;
    const int t0 = tid >> 2;               // 0..63
    for (int t = t0; t < L_LEN; t += 64) {
        size_t g = base + (size_t)t * D_DIM + c2;
        float2 q2 = *(const float2*)(Q + g);
        float2 k2 = *(const float2*)(K + g);
        xre[c2 * PADA + t] = q2.x;  xre[(c2 + 1) * PADA + t] = q2.y;
        xim[c2 * PADA + t] = k2.x;  xim[(c2 + 1) * PADA + t] = k2.y;
    }
    __syncthreads();

    float* re = xre + warp * PADA;
    float* im = xim + warp * PADA;

    // base twiddle: t1 = w^lane, w = exp(-2*pi*i/512). Higher powers are
    // recomputed per stage (keeps register liveness low for occ=5).
    float t1i, t1r;
    __sincosf((float)lane * -0.01227184630f, &t1i, &t1r);

    // load channel into registers, layout A (u = r*32 + lane)
    float cre[16], cim[16];
    #pragma unroll
    for (int r = 0; r < 16; ++r) {
        cre[r] = re[r * 32 + lane];
        cim[r] = im[r * 32 + lane];
    }
    __syncwarp();

    // ---- forward DIF, layout A ----
    #pragma unroll
    for (int r = 0; r < 8; ++r) {          // s=8, m=256
        float wr = t1r * C16R[r] - t1i * C16I[r];
        float wi = t1r * C16I[r] + t1i * C16R[r];
        bf_dif(cre[r], cim[r], cre[r + 8], cim[r + 8], wr, wi);
    }
    {                                       // s=7, m=128  (t2 = t1^2)
        float t2r = t1r * t1r - t1i * t1i, t2i = 2.0f * t1r * t1i;
        #pragma unroll
        for (int g = 0; g < 2; ++g)
            #pragma unroll
            for (int j = 0; j < 4; ++j) {
                float wr = t2r * C16R[2 * j] - t2i * C16I[2 * j];
                float wi = t2r * C16I[2 * j] + t2i * C16R[2 * j];
                int r = g * 8 + j;
                bf_dif(cre[r], cim[r], cre[r + 4], cim[r + 4], wr, wi);
            }
        float t4r = t2r * t2r - t2i * t2i, t4i = 2.0f * t2r * t2i;   // s=6, m=64
        #pragma unroll
        for (int g = 0; g < 4; ++g) {
            int r = g * 4;
            bf_dif(cre[r],     cim[r],     cre[r + 2], cim[r + 2], t4r, t4i);
            bf_dif(cre[r + 1], cim[r + 1], cre[r + 3], cim[r + 3], t4i, -t4r);
        }
        float t8r = t4r * t4r - t4i * t4i, t8i = 2.0f * t4r * t4i;   // s=5, m=32
        #pragma unroll
        for (int g = 0; g < 8; ++g) {
            int r = g * 2;
            bf_dif(cre[r], cim[r], cre[r + 1], cim[r + 1], t8r, t8i);
        }
    }
    // ---- forward: shuffle stage m=16 ----
    {
        float swi, swr;
        __sincosf((float)(lane & 15) * -0.19634954085f, &swi, &swr);
        const bool hi = (lane & 16) != 0;
        #pragma unroll
        for (int r = 0; r < 16; ++r) {
            float orr = __shfl_xor_sync(0xffffffffu, cre[r], 16);
            float oii = __shfl_xor_sync(0xffffffffu, cim[r], 16);
            float sr = cre[r] + orr, si = cim[r] + oii;
            float tr = orr - cre[r], ti = oii - cim[r];    // (a-b) on hi lanes
            float pr = tr * swr - ti * swi;
            float pi = tr * swi + ti * swr;
            cre[r] = hi ? pr : sr;
            cim[r] = hi ? pi : si;
        }
    }
    // ---- transpose A -> B through swizzled SMEM ----
    #pragma unroll
    for (int r = 0; r < 16; ++r) {
        int v = swz(r * 32 + lane);
        re[v] = cre[r];  im[v] = cim[r];
    }
    __syncwarp();
    #pragma unroll
    for (int r = 0; r < 16; ++r) {
        int v = swz(lane * 16 + r);
        cre[r] = re[v];  cim[r] = im[v];
    }
    __syncwarp();
    // ---- forward DIF, layout B (all-constant twiddles) ----
    #pragma unroll
    for (int r = 0; r < 8; ++r) {          // s=3, m=8: tw = C16[r]
        if (r == 0)      bf_dif1 (cre[0], cim[0], cre[8],  cim[8]);
        else if (r == 4) bf_difmi(cre[4], cim[4], cre[12], cim[12]);
        else bf_dif(cre[r], cim[r], cre[r + 8], cim[r + 8], C16R[r], C16I[r]);
    }
    #pragma unroll
    for (int g = 0; g < 2; ++g)            // s=2, m=4: tw = C16[2j]
        #pragma unroll
        for (int j = 0; j < 4; ++j) {
            int r = g * 8 + j;
            if (j == 0)      bf_dif1 (cre[r], cim[r], cre[r + 4], cim[r + 4]);
            else if (j == 2) bf_difmi(cre[r], cim[r], cre[r + 4], cim[r + 4]);
            else bf_dif(cre[r], cim[r], cre[r + 4], cim[r + 4], C16R[2 * j], C16I[2 * j]);
        }
    #pragma unroll
    for (int g = 0; g < 4; ++g) {          // s=1, m=2: tw = 1 or -i
        int r = g * 4;
        bf_dif1 (cre[r],     cim[r],     cre[r + 2], cim[r + 2]);
        bf_difmi(cre[r + 1], cim[r + 1], cre[r + 3], cim[r + 3]);
    }
    #pragma unroll
    for (int g = 0; g < 8; ++g)            // s=0, m=1: tw = 1
        bf_dif1(cre[g * 2], cim[g * 2], cre[g * 2 + 1], cim[g * 2 + 1]);

    // ---- spill (layout B) for bit-reversed Hermitian cross-spectrum ----
    #pragma unroll
    for (int r = 0; r < 16; ++r) {
        int v = swz(lane * 16 + r);
        re[v] = cre[r];  im[v] = cim[r];
    }
    __syncwarp();

    const float inv_n = 1.0f / 512.0f;
    #pragma unroll
    for (int k = 0; k < 8; ++k) {
        int f = 1 + lane + (k << 5);          // f in [1, 256]
        if (f == 256) {
            int pb = swz(brev9(256));
            float qr = re[pb], kr = im[pb];   // both real at Nyquist
            re[pb] = qr * kr * inv_n;
            im[pb] = 0.f;
        } else {
            int p1 = swz(brev9(f));
            int p2 = swz(brev9(512 - f));
            float ar = re[p1], ai = im[p1];
            float br = re[p2], bi = -im[p2];              // conj(X[512-f])
            float qr = 0.5f * (ar + br), qi = 0.5f * (ai + bi);
            float dr = ar - br,          di = ai - bi;
            float kr = 0.5f * di,        ki = -0.5f * dr;  // (A-B)/(2i)
            float pr = (qr * kr + qi * ki) * inv_n;
            float pi = (qi * kr - qr * ki) * inv_n;
            re[p1] = pr;  im[p1] = pi;
            re[p2] = pr;  im[p2] = -pi;                    // Hermitian partner
        }
    }
    if (lane == 0) {                          // f = 0 (DC), both real
        float v = re[0] * im[0] * inv_n;
        re[0] = v; im[0] = 0.f;
    }
    __syncwarp();

    #pragma unroll
    for (int r = 0; r < 16; ++r) {
        int v = swz(lane * 16 + r);
        cre[r] = re[v];  cim[r] = im[v];
    }
    __syncwarp();

    // ---- inverse DIT, layout B ----
    #pragma unroll
    for (int g = 0; g < 8; ++g)            // s=0
        bf_dit1(cre[g * 2], cim[g * 2], cre[g * 2 + 1], cim[g * 2 + 1]);
    #pragma unroll
    for (int g = 0; g < 4; ++g) {          // s=1
        int r = g * 4;
        bf_dit1 (cre[r],     cim[r],     cre[r + 2], cim[r + 2]);
        bf_ditmi(cre[r + 1], cim[r + 1], cre[r + 3], cim[r + 3]);
    }
    #pragma unroll
    for (int g = 0; g < 2; ++g)            // s=2
        #pragma unroll
        for (int j = 0; j < 4; ++j) {
            int r = g * 8 + j;
            if (j == 0)      bf_dit1 (cre[r], cim[r], cre[r + 4], cim[r + 4]);
            else if (j == 2) bf_ditmi(cre[r], cim[r], cre[r + 4], cim[r + 4]);
            else bf_dit(cre[r], cim[r], cre[r + 4], cim[r + 4], C16R[2 * j], C16I[2 * j]);
        }
    #pragma unroll
    for (int r = 0; r < 8; ++r) {          // s=3
        if (r == 0)      bf_dit1 (cre[0], cim[0], cre[8],  cim[8]);
        else if (r == 4) bf_ditmi(cre[4], cim[4], cre[12], cim[12]);
        else bf_dit(cre[r], cim[r], cre[r + 8], cim[r + 8], C16R[r], C16I[r]);
    }
    // ---- transpose B -> A through swizzled SMEM ----
    #pragma unroll
    for (int r = 0; r < 16; ++r) {
        int v = swz(lane * 16 + r);
        re[v] = cre[r];  im[v] = cim[r];
    }
    __syncwarp();
    #pragma unroll
    for (int r = 0; r < 16; ++r) {
        int v = swz(r * 32 + lane);
        cre[r] = re[v];  cim[r] = im[v];
    }
    __syncwarp();
    // ---- inverse: shuffle stage m=16 (conj tw, recomputed) ----
    {
        float swi, swr;
        __sincosf((float)(lane & 15) * -0.19634954085f, &swi, &swr);
        const float wr = swr, wi = -swi;
        const bool hi = (lane & 16) != 0;
        #pragma unroll
        for (int r = 0; r < 16; ++r) {
            float rr = cre[r] * wr - cim[r] * wi;   // hi lanes pre-rotate b*conj(w)
            float ri = cre[r] * wi + cim[r] * wr;
            float vr = hi ? rr : cre[r];
            float vi = hi ? ri : cim[r];
            float orr = __shfl_xor_sync(0xffffffffu, vr, 16);
            float oii = __shfl_xor_sync(0xffffffffu, vi, 16);
            cre[r] = hi ? (orr - vr) : (vr + orr);
            cim[r] = hi ? (oii - vi) : (vi + oii);
        }
    }
    // ---- inverse DIT, layout A (twiddle bases recomputed from t1) ----
    {
        float t2r = t1r * t1r - t1i * t1i, t2i = 2.0f * t1r * t1i;
        float t4r = t2r * t2r - t2i * t2i, t4i = 2.0f * t2r * t2i;
        float t8r = t4r * t4r - t4i * t4i, t8i = 2.0f * t4r * t4i;
        #pragma unroll
        for (int g = 0; g < 8; ++g) {      // s=5
            int r = g * 2;
            bf_dit(cre[r], cim[r], cre[r + 1], cim[r + 1], t8r, t8i);
        }
        #pragma unroll
        for (int g = 0; g < 4; ++g) {      // s=6
            int r = g * 4;
            bf_dit(cre[r],     cim[r],     cre[r + 2], cim[r + 2], t4r, t4i);
            bf_dit(cre[r + 1], cim[r + 1], cre[r + 3], cim[r + 3], t4i, -t4r);
        }
        #pragma unroll
        for (int g = 0; g < 2; ++g)        // s=7
            #pragma unroll
            for (int j = 0; j < 4; ++j) {
                float wr = t2r * C16R[2 * j] - t2i * C16I[2 * j];
                float wi = t2r * C16I[2 * j] + t2i * C16R[2 * j];
                int r = g * 8 + j;
                bf_dit(cre[r], cim[r], cre[r + 4], cim[r + 4], wr, wi);
            }
        #pragma unroll
        for (int r = 0; r < 8; ++r) {      // s=8
            float wr = t1r * C16R[r] - t1i * C16I[r];
            float wi = t1r * C16I[r] + t1i * C16R[r];
            bf_dit(cre[r], cim[r], cre[r + 8], cim[r + 8], wr, wi);
        }
    }
    // corr (natural order) now in cre[], index u = r*32 + lane

    // ---- top-12: monotonic uint keys + REDUX warp argmax ----
    unsigned key[16];
    #pragma unroll
    for (int r = 0; r < 16; ++r) {
        unsigned u = __float_as_uint(cre[r]);
        key[r] = u ^ ((unsigned)((int)u >> 31) | 0x80000000u);
    }
    float wv[TOPK]; int wx[TOPK];
    #pragma unroll
    for (int it = 0; it < TOPK; ++it) {
        unsigned a0 = max(key[0],  key[1]),  a1 = max(key[2],  key[3]);
        unsigned a2 = max(key[4],  key[5]),  a3 = max(key[6],  key[7]);
        unsigned a4 = max(key[8],  key[9]),  a5 = max(key[10], key[11]);
        unsigned a6 = max(key[12], key[13]), a7 = max(key[14], key[15]);
        unsigned b0 = max(a0, a1), b1 = max(a2, a3), b2 = max(a4, a5), b3 = max(a6, a7);
        unsigned lmax = max(max(b0, b1), max(b2, b3));
        unsigned M = __reduce_max_sync(0xffffffffu, lmax);
        unsigned ball = __ballot_sync(0xffffffffu, lmax == M);
        int wl = __ffs((int)ball) - 1;
        bool pm = (lane == wl);
        int wr = 0;
        #pragma unroll
        for (int r = 0; r < 16; ++r) {
            bool p = pm && (key[r] == M);
            if (p) { wr = r; key[r] = 0u; pm = false; }
        }
        wr = __shfl_sync(0xffffffffu, wr, wl);
        unsigned ub = (M & 0x80000000u) ? (M & 0x7fffffffu) : ~M;
        wv[it] = __uint_as_float(ub);
        wx[it] = (wr << 5) | wl;
    }

    // ---- softmax over the 12 selected (every lane holds all 12) ----
    {
        float mx = wv[0], ssum = 0.f;
        #pragma unroll
        for (int i = 0; i < TOPK; ++i) { wv[i] = __expf(wv[i] - mx); ssum += wv[i]; }
        float inv = 1.0f / ssum;
        #pragma unroll
        for (int i = 0; i < TOPK; ++i) wv[i] *= inv;
    }

    // ---- load V into the dead xim tile (coalesced float2, transposed) ----
    __syncthreads();                          // all warps done with xre/xim FFT use
    for (int t = t0; t < L_LEN; t += 64) {
        size_t g = base + (size_t)t * D_DIM + c2;
        float2 v2 = *(const float2*)(V + g);
        xim[c2 * PADA + t] = v2.x;  xim[(c2 + 1) * PADA + t] = v2.y;
    }
    __syncthreads();

    // ---- gather: out[l] = sum_i w_i * V[min(idx_i + l, 511)] (own channel) ----
    {
        unsigned vbase = (unsigned)__cvta_generic_to_shared(xim + warp * PADA);
        unsigned alim  = vbase + 511u * 4u;
        unsigned lane4 = (unsigned)lane << 2;
        unsigned api[TOPK];
        #pragma unroll
        for (int i = 0; i < TOPK; ++i)
            api[i] = vbase + ((unsigned)wx[i] << 2) + lane4;

        float* orow = xre + warp * PADA;      // xre row is dead -> out tile
        #pragma unroll
        for (int p = 0; p < 16; ++p) {
            float acc = 0.f;
            #pragma unroll
            for (int i = 0; i < TOPK; ++i) {
                unsigned a = api[i] + (unsigned)(p * 128);
                a = a < alim ? a : alim;      // clamp folded into address
                float v;
                asm volatile("ld.shared.f32 %0, [%1];" : "=f"(v) : "r"(a));
                acc += wv[i] * v;
            }
            orow[lane + (p << 5)] = acc;
        }
    }
    __syncthreads();

    // ---- cooperative coalesced float2 store ----
    for (int t = t0; t < L_LEN; t += 64) {
        float2 o2;
        o2.x = xre[c2 * PADA + t];
        o2.y = xre[(c2 + 1) * PADA + t];
        *(float2*)(out + base + (size_t)t * D_DIM + c2) = o2;
    }
}

// ---------------------------------------------------------------------------
extern "C" void kernel_launch(void* const* d_in, const int* in_sizes, int n_in,
                              void* d_out, int out_size) {
    (void)n_in; (void)out_size;
    const float* Q = (const float*)d_in[0];
    const float* K = (const float*)d_in[1];
    const float* V = (const float*)d_in[2];
    float* out = (float*)d_out;

    const int B = in_sizes[0] / (L_LEN * D_DIM);   // 16

    const int SMEM = (2 * CPA * PADA) * (int)sizeof(float);   // 33024 B
    cudaFuncSetAttribute(fused_autocorr_kernel,
                         cudaFuncAttributeMaxDynamicSharedMemorySize, SMEM);

    dim3 grid(B * 8, 512 / CPA);   // (128, 64)
    fused_autocorr_kernel<<<grid, 256, SMEM>>>(Q, K, V, out);
}

// round 6
// speedup vs baseline: 4.6893x; 1.1331x over previous
#include <cuda_runtime.h>
#include <math_constants.h>

#define L_LEN  512
#define D_DIM  4096
#define TOPK   12
#define CPA    8           // channels per block
#define PADA   516         // row pitch (%32==4 -> conflict-free coop transpose; even -> 8B align)

__device__ __forceinline__ int brev9(int x) { return (int)(__brev((unsigned)x) >> 23); }
// XOR swizzle: conflict-free for both {r*32+lane} and {lane*16+r} warp patterns
__device__ __forceinline__ int swz(int u)   { return u ^ (u >> 5); }

// 16th roots of unity: C16[j] = exp(-2*pi*i*j/16)
__device__ constexpr float C16R[8] = { 1.0f,  0.92387953251f,  0.70710678119f,  0.38268343236f,
                                       0.0f, -0.38268343236f, -0.70710678119f, -0.92387953251f };
__device__ constexpr float C16I[8] = { 0.0f, -0.38268343236f, -0.70710678119f, -0.92387953251f,
                                      -1.0f, -0.92387953251f, -0.70710678119f, -0.38268343236f };

// DIF butterfly: (a,b) -> (a+b, (a-b)*w)
__device__ __forceinline__ void bf_dif(float& ar, float& ai, float& br, float& bi,
                                       float wr, float wi) {
    float tr = ar - br, ti = ai - bi;
    ar += br; ai += bi;
    br = tr * wr - ti * wi;
    bi = tr * wi + ti * wr;
}
__device__ __forceinline__ void bf_dif1(float& ar, float& ai, float& br, float& bi) {
    float tr = ar - br, ti = ai - bi;
    ar += br; ai += bi; br = tr; bi = ti;
}
__device__ __forceinline__ void bf_difmi(float& ar, float& ai, float& br, float& bi) {
    float tr = ar - br, ti = ai - bi;        // *( -i ): (tr,ti) -> (ti, -tr)
    ar += br; ai += bi; br = ti; bi = -tr;
}
// DIT (inverse) butterfly with conj(w): (a,b) -> (a + b*conj(w), a - b*conj(w))
__device__ __forceinline__ void bf_dit(float& ar, float& ai, float& br, float& bi,
                                       float wr, float wi) {
    float rr = br * wr + bi * wi;
    float ri = bi * wr - br * wi;
    br = ar - rr; bi = ai - ri;
    ar += rr; ai += ri;
}
__device__ __forceinline__ void bf_dit1(float& ar, float& ai, float& br, float& bi) {
    float rr = br, ri = bi;
    br = ar - rr; bi = ai - ri;
    ar += rr; ai += ri;
}
__device__ __forceinline__ void bf_ditmi(float& ar, float& ai, float& br, float& bi) {
    float rr = -bi, ri = br;                 // b * conj(-i) = b * i
    br = ar - rr; bi = ai - ri;
    ar += rr; ai += ri;
}

// ---------------------------------------------------------------------------
// Fused: per-channel FFT cross-correlation -> top-12 + softmax -> gather of V.
// One warp per channel, 8 channels / 256 threads, 2 smem tiles total; V is
// double-buffered (even + shifted copy) into the dead FFT tiles so the gather
// runs on aligned ld.shared.v2 pairs.
// ---------------------------------------------------------------------------
extern "C" __global__ void __launch_bounds__(256, 5)
fused_autocorr_kernel(const float* __restrict__ Q, const float* __restrict__ K,
                      const float* __restrict__ V, float* __restrict__ out) {
    extern __shared__ float smbuf[];
    float* xre = smbuf;                    // [CPA][PADA]  FFT re / V even buf / out tile
    float* xim = xre + CPA * PADA;         // [CPA][PADA]  FFT im / V shift buf

    const int tid  = threadIdx.x;
    const int warp = tid >> 5;
    const int lane = tid & 31;
    const int bh   = blockIdx.x;
    const int b    = bh >> 3;
    const int h    = bh & 7;
    const int cbase = blockIdx.y * CPA;

    // cooperative float2 coalesced loads (Q,K only), transposed channel-major
    const size_t base = (size_t)b * L_LEN * D_DIM + (size_t)h * 512 + cbase;
    const int c2 = (tid & 3) << 1;
    const int t0 = tid >> 2;               // 0..63
    for (int t = t0; t < L_LEN; t += 64) {
        size_t g = base + (size_t)t * D_DIM + c2;
        float2 q2 = *(const float2*)(Q + g);
        float2 k2 = *(const float2*)(K + g);
        xre[c2 * PADA + t] = q2.x;  xre[(c2 + 1) * PADA + t] = q2.y;
        xim[c2 * PADA + t] = k2.x;  xim[(c2 + 1) * PADA + t] = k2.y;
    }
    __syncthreads();

    float* re = xre + warp * PADA;
    float* im = xim + warp * PADA;

    // base twiddle: t1 = w^lane, w = exp(-2*pi*i/512)
    float t1i, t1r;
    __sincosf((float)lane * -0.01227184630f, &t1i, &t1r);

    // load channel into registers, layout A (u = r*32 + lane)
    float cre[16], cim[16];
    #pragma unroll
    for (int r = 0; r < 16; ++r) {
        cre[r] = re[r * 32 + lane];
        cim[r] = im[r * 32 + lane];
    }
    __syncwarp();

    // ---- forward DIF, layout A ----
    #pragma unroll
    for (int r = 0; r < 8; ++r) {          // s=8, m=256
        float wr = t1r * C16R[r] - t1i * C16I[r];
        float wi = t1r * C16I[r] + t1i * C16R[r];
        bf_dif(cre[r], cim[r], cre[r + 8], cim[r + 8], wr, wi);
    }
    {                                       // s=7..5 (bases recomputed from t1)
        float t2r = t1r * t1r - t1i * t1i, t2i = 2.0f * t1r * t1i;
        #pragma unroll
        for (int g = 0; g < 2; ++g)
            #pragma unroll
            for (int j = 0; j < 4; ++j) {
                float wr = t2r * C16R[2 * j] - t2i * C16I[2 * j];
                float wi = t2r * C16I[2 * j] + t2i * C16R[2 * j];
                int r = g * 8 + j;
                bf_dif(cre[r], cim[r], cre[r + 4], cim[r + 4], wr, wi);
            }
        float t4r = t2r * t2r - t2i * t2i, t4i = 2.0f * t2r * t2i;   // s=6
        #pragma unroll
        for (int g = 0; g < 4; ++g) {
            int r = g * 4;
            bf_dif(cre[r],     cim[r],     cre[r + 2], cim[r + 2], t4r, t4i);
            bf_dif(cre[r + 1], cim[r + 1], cre[r + 3], cim[r + 3], t4i, -t4r);
        }
        float t8r = t4r * t4r - t4i * t4i, t8i = 2.0f * t4r * t4i;   // s=5
        #pragma unroll
        for (int g = 0; g < 8; ++g) {
            int r = g * 2;
            bf_dif(cre[r], cim[r], cre[r + 1], cim[r + 1], t8r, t8i);
        }
    }
    // ---- forward: shuffle stage m=16 ----
    {
        float swi, swr;
        __sincosf((float)(lane & 15) * -0.19634954085f, &swi, &swr);
        const bool hi = (lane & 16) != 0;
        #pragma unroll
        for (int r = 0; r < 16; ++r) {
            float orr = __shfl_xor_sync(0xffffffffu, cre[r], 16);
            float oii = __shfl_xor_sync(0xffffffffu, cim[r], 16);
            float sr = cre[r] + orr, si = cim[r] + oii;
            float tr = orr - cre[r], ti = oii - cim[r];    // (a-b) on hi lanes
            float pr = tr * swr - ti * swi;
            float pi = tr * swi + ti * swr;
            cre[r] = hi ? pr : sr;
            cim[r] = hi ? pi : si;
        }
    }
    // ---- transpose A -> B through swizzled SMEM ----
    #pragma unroll
    for (int r = 0; r < 16; ++r) {
        int v = swz(r * 32 + lane);
        re[v] = cre[r];  im[v] = cim[r];
    }
    __syncwarp();
    #pragma unroll
    for (int r = 0; r < 16; ++r) {
        int v = swz(lane * 16 + r);
        cre[r] = re[v];  cim[r] = im[v];
    }
    __syncwarp();
    // ---- forward DIF, layout B (all-constant twiddles) ----
    #pragma unroll
    for (int r = 0; r < 8; ++r) {          // s=3, m=8
        if (r == 0)      bf_dif1 (cre[0], cim[0], cre[8],  cim[8]);
        else if (r == 4) bf_difmi(cre[4], cim[4], cre[12], cim[12]);
        else bf_dif(cre[r], cim[r], cre[r + 8], cim[r + 8], C16R[r], C16I[r]);
    }
    #pragma unroll
    for (int g = 0; g < 2; ++g)            // s=2, m=4
        #pragma unroll
        for (int j = 0; j < 4; ++j) {
            int r = g * 8 + j;
            if (j == 0)      bf_dif1 (cre[r], cim[r], cre[r + 4], cim[r + 4]);
            else if (j == 2) bf_difmi(cre[r], cim[r], cre[r + 4], cim[r + 4]);
            else bf_dif(cre[r], cim[r], cre[r + 4], cim[r + 4], C16R[2 * j], C16I[2 * j]);
        }
    #pragma unroll
    for (int g = 0; g < 4; ++g) {          // s=1, m=2
        int r = g * 4;
        bf_dif1 (cre[r],     cim[r],     cre[r + 2], cim[r + 2]);
        bf_difmi(cre[r + 1], cim[r + 1], cre[r + 3], cim[r + 3]);
    }
    #pragma unroll
    for (int g = 0; g < 8; ++g)            // s=0, m=1
        bf_dif1(cre[g * 2], cim[g * 2], cre[g * 2 + 1], cim[g * 2 + 1]);

    // ---- spill (layout B) for bit-reversed Hermitian cross-spectrum ----
    #pragma unroll
    for (int r = 0; r < 16; ++r) {
        int v = swz(lane * 16 + r);
        re[v] = cre[r];  im[v] = cim[r];
    }
    __syncwarp();

    const float inv_n = 1.0f / 512.0f;
    #pragma unroll
    for (int k = 0; k < 8; ++k) {
        int f = 1 + lane + (k << 5);          // f in [1, 256]
        if (f == 256) {
            int pb = swz(brev9(256));
            float qr = re[pb], kr = im[pb];   // both real at Nyquist
            re[pb] = qr * kr * inv_n;
            im[pb] = 0.f;
        } else {
            int p1 = swz(brev9(f));
            int p2 = swz(brev9(512 - f));
            float ar = re[p1], ai = im[p1];
            float br = re[p2], bi = -im[p2];              // conj(X[512-f])
            float qr = 0.5f * (ar + br), qi = 0.5f * (ai + bi);
            float dr = ar - br,          di = ai - bi;
            float kr = 0.5f * di,        ki = -0.5f * dr;  // (A-B)/(2i)
            float pr = (qr * kr + qi * ki) * inv_n;
            float pi = (qi * kr - qr * ki) * inv_n;
            re[p1] = pr;  im[p1] = pi;
            re[p2] = pr;  im[p2] = -pi;                    // Hermitian partner
        }
    }
    if (lane == 0) {                          // f = 0 (DC), both real
        float v = re[0] * im[0] * inv_n;
        re[0] = v; im[0] = 0.f;
    }
    __syncwarp();

    #pragma unroll
    for (int r = 0; r < 16; ++r) {
        int v = swz(lane * 16 + r);
        cre[r] = re[v];  cim[r] = im[v];
    }
    __syncwarp();

    // ---- inverse DIT, layout B ----
    #pragma unroll
    for (int g = 0; g < 8; ++g)            // s=0
        bf_dit1(cre[g * 2], cim[g * 2], cre[g * 2 + 1], cim[g * 2 + 1]);
    #pragma unroll
    for (int g = 0; g < 4; ++g) {          // s=1
        int r = g * 4;
        bf_dit1 (cre[r],     cim[r],     cre[r + 2], cim[r + 2]);
        bf_ditmi(cre[r + 1], cim[r + 1], cre[r + 3], cim[r + 3]);
    }
    #pragma unroll
    for (int g = 0; g < 2; ++g)            // s=2
        #pragma unroll
        for (int j = 0; j < 4; ++j) {
            int r = g * 8 + j;
            if (j == 0)      bf_dit1 (cre[r], cim[r], cre[r + 4], cim[r + 4]);
            else if (j == 2) bf_ditmi(cre[r], cim[r], cre[r + 4], cim[r + 4]);
            else bf_dit(cre[r], cim[r], cre[r + 4], cim[r + 4], C16R[2 * j], C16I[2 * j]);
        }
    #pragma unroll
    for (int r = 0; r < 8; ++r) {          // s=3
        if (r == 0)      bf_dit1 (cre[0], cim[0], cre[8],  cim[8]);
        else if (r == 4) bf_ditmi(cre[4], cim[4], cre[12], cim[12]);
        else bf_dit(cre[r], cim[r], cre[r + 8], cim[r + 8], C16R[r], C16I[r]);
    }
    // ---- transpose B -> A through swizzled SMEM ----
    #pragma unroll
    for (int r = 0; r < 16; ++r) {
        int v = swz(lane * 16 + r);
        re[v] = cre[r];  im[v] = cim[r];
    }
    __syncwarp();
    #pragma unroll
    for (int r = 0; r < 16; ++r) {
        int v = swz(r * 32 + lane);
        cre[r] = re[v];  cim[r] = im[v];
    }
    __syncwarp();
    // ---- inverse: shuffle stage m=16 (conj tw) ----
    {
        float swi, swr;
        __sincosf((float)(lane & 15) * -0.19634954085f, &swi, &swr);
        const float wr = swr, wi = -swi;
        const bool hi = (lane & 16) != 0;
        #pragma unroll
        for (int r = 0; r < 16; ++r) {
            float rr = cre[r] * wr - cim[r] * wi;   // hi lanes pre-rotate b*conj(w)
            float ri = cre[r] * wi + cim[r] * wr;
            float vr = hi ? rr : cre[r];
            float vi = hi ? ri : cim[r];
            float orr = __shfl_xor_sync(0xffffffffu, vr, 16);
            float oii = __shfl_xor_sync(0xffffffffu, vi, 16);
            cre[r] = hi ? (orr - vr) : (vr + orr);
            cim[r] = hi ? (oii - vi) : (vi + oii);
        }
    }
    // ---- inverse DIT, layout A ----
    {
        float t2r = t1r * t1r - t1i * t1i, t2i = 2.0f * t1r * t1i;
        float t4r = t2r * t2r - t2i * t2i, t4i = 2.0f * t2r * t2i;
        float t8r = t4r * t4r - t4i * t4i, t8i = 2.0f * t4r * t4i;
        #pragma unroll
        for (int g = 0; g < 8; ++g) {      // s=5
            int r = g * 2;
            bf_dit(cre[r], cim[r], cre[r + 1], cim[r + 1], t8r, t8i);
        }
        #pragma unroll
        for (int g = 0; g < 4; ++g) {      // s=6
            int r = g * 4;
            bf_dit(cre[r],     cim[r],     cre[r + 2], cim[r + 2], t4r, t4i);
            bf_dit(cre[r + 1], cim[r + 1], cre[r + 3], cim[r + 3], t4i, -t4r);
        }
        #pragma unroll
        for (int g = 0; g < 2; ++g)        // s=7
            #pragma unroll
            for (int j = 0; j < 4; ++j) {
                float wr = t2r * C16R[2 * j] - t2i * C16I[2 * j];
                float wi = t2r * C16I[2 * j] + t2i * C16R[2 * j];
                int r = g * 8 + j;
                bf_dit(cre[r], cim[r], cre[r + 4], cim[r + 4], wr, wi);
            }
        #pragma unroll
        for (int r = 0; r < 8; ++r) {      // s=8
            float wr = t1r * C16R[r] - t1i * C16I[r];
            float wi = t1r * C16I[r] + t1i * C16R[r];
            bf_dit(cre[r], cim[r], cre[r + 8], cim[r + 8], wr, wi);
        }
    }
    // corr (natural order) now in cre[], index u = r*32 + lane

    // ---- spill corr row (natural order) for exact value refetch ----
    #pragma unroll
    for (int r = 0; r < 16; ++r)
        re[r * 32 + lane] = cre[r];
    __syncwarp();

    // ---- top-12: position-packed unique keys + strict-less filter + REDUX ----
    // kp = (monotonic_float & ~511) | (511 - pos): max key = max value,
    // truncated-value ties resolve to the smaller position (stable top_k).
    unsigned kp[16];
    {
        const int il = 31 - lane;
        #pragma unroll
        for (int r = 0; r < 16; ++r) {
            unsigned u = __float_as_uint(cre[r]);
            unsigned mono = u ^ ((unsigned)((int)u >> 31) | 0x80000000u);
            kp[r] = (mono & 0xFFFFFE00u) | (unsigned)(480 - 32 * r + il);
        }
    }
    float wv[TOPK]; int wx[TOPK];
    unsigned Mprev = 0xFFFFFFFFu;
    #pragma unroll
    for (int it = 0; it < TOPK; ++it) {
        unsigned f0  = kp[0]  < Mprev ? kp[0]  : 0u;
        unsigned f1  = kp[1]  < Mprev ? kp[1]  : 0u;
        unsigned f2  = kp[2]  < Mprev ? kp[2]  : 0u;
        unsigned f3  = kp[3]  < Mprev ? kp[3]  : 0u;
        unsigned f4  = kp[4]  < Mprev ? kp[4]  : 0u;
        unsigned f5  = kp[5]  < Mprev ? kp[5]  : 0u;
        unsigned f6  = kp[6]  < Mprev ? kp[6]  : 0u;
        unsigned f7  = kp[7]  < Mprev ? kp[7]  : 0u;
        unsigned f8  = kp[8]  < Mprev ? kp[8]  : 0u;
        unsigned f9  = kp[9]  < Mprev ? kp[9]  : 0u;
        unsigned f10 = kp[10] < Mprev ? kp[10] : 0u;
        unsigned f11 = kp[11] < Mprev ? kp[11] : 0u;
        unsigned f12 = kp[12] < Mprev ? kp[12] : 0u;
        unsigned f13 = kp[13] < Mprev ? kp[13] : 0u;
        unsigned f14 = kp[14] < Mprev ? kp[14] : 0u;
        unsigned f15 = kp[15] < Mprev ? kp[15] : 0u;
        unsigned a0 = max(f0, f1),   a1 = max(f2, f3);
        unsigned a2 = max(f4, f5),   a3 = max(f6, f7);
        unsigned a4 = max(f8, f9),   a5 = max(f10, f11);
        unsigned a6 = max(f12, f13), a7 = max(f14, f15);
        unsigned b0 = max(a0, a1), b1 = max(a2, a3);
        unsigned b2 = max(a4, a5), b3 = max(a6, a7);
        unsigned lmax = max(max(b0, b1), max(b2, b3));
        unsigned M = __reduce_max_sync(0xffffffffu, lmax);
        Mprev = M;
        int pos = 511 - (int)(M & 511u);
        wx[it] = pos;
        wv[it] = re[pos];                 // exact value, broadcast LDS
    }

    // ---- softmax over the 12 selected (every lane holds all 12) ----
    {
        float mx = wv[0], ssum = 0.f;
        #pragma unroll
        for (int i = 0; i < TOPK; ++i) { wv[i] = __expf(wv[i] - mx); ssum += wv[i]; }
        float inv = 1.0f / ssum;
        #pragma unroll
        for (int i = 0; i < TOPK; ++i) wv[i] *= inv;
    }

    // ---- build V double buffer in the dead FFT tiles ----
    // even buf (xre row): ev[t] = v[t], ev[512] = ev[513] = v[511]
    // shift buf (xim row): sh[t] = v[t+1] (t<=510), sh[511] = v[511]
    __syncthreads();                          // all warps done with xre/xim + corr rows
    for (int t = t0; t < L_LEN; t += 64) {
        size_t g = base + (size_t)t * D_DIM + c2;
        float2 v2 = *(const float2*)(V + g);
        xre[c2 * PADA + t] = v2.x;
        xre[(c2 + 1) * PADA + t] = v2.y;
        if (t > 0) {
            xim[c2 * PADA + (t - 1)] = v2.x;
            xim[(c2 + 1) * PADA + (t - 1)] = v2.y;
        }
        if (t == 511) {
            xre[c2 * PADA + 512] = v2.x;        xre[c2 * PADA + 513] = v2.x;
            xre[(c2 + 1) * PADA + 512] = v2.y;  xre[(c2 + 1) * PADA + 513] = v2.y;
            xim[c2 * PADA + 511] = v2.x;
            xim[(c2 + 1) * PADA + 511] = v2.y;
        }
    }
    __syncthreads();

    // ---- pair-gather: out[l] = sum_i w_i * v[min(idx_i + l, 511)] ----
    // l = 2*lane + 64*pp; aligned v2 pair from parity-matched buffer.
    {
        unsigned evb = (unsigned)__cvta_generic_to_shared(xre + warp * PADA);
        unsigned shb = (unsigned)__cvta_generic_to_shared(xim + warp * PADA);
        unsigned amaxE = evb + 512u * 4u;     // clamped pair = (v511, v511)
        unsigned amaxO = shb + 510u * 4u;
        unsigned lane8 = (unsigned)lane << 3;

        float acc[16];
        #pragma unroll
        for (int j = 0; j < 16; ++j) acc[j] = 0.f;

        #pragma unroll
        for (int i = 0; i < TOPK; ++i) {
            int idx = wx[i];
            bool odd = (idx & 1) != 0;
            unsigned rowb = odd ? shb : evb;
            unsigned amax = odd ? amaxO : amaxE;
            unsigned ab = rowb + (((unsigned)idx & ~1u) << 2) + lane8;
            float w = wv[i];
            #pragma unroll
            for (int pp = 0; pp < 8; ++pp) {
                unsigned a = ab + (unsigned)(pp * 256);
                a = a < amax ? a : amax;
                float vx, vy;
                asm volatile("ld.shared.v2.f32 {%0, %1}, [%2];"
                             : "=f"(vx), "=f"(vy) : "r"(a));
                acc[2 * pp]     += w * vx;
                acc[2 * pp + 1] += w * vy;
            }
        }
        __syncwarp();                         // all lanes done reading own rows
        #pragma unroll
        for (int pp = 0; pp < 8; ++pp) {      // overwrite own even row with out
            unsigned a = evb + lane8 + (unsigned)(pp * 256);
            asm volatile("st.shared.v2.f32 [%0], {%1, %2};"
                         :: "r"(a), "f"(acc[2 * pp]), "f"(acc[2 * pp + 1]));
        }
    }
    __syncthreads();

    // ---- cooperative coalesced float2 store ----
    for (int t = t0; t < L_LEN; t += 64) {
        float2 o2;
        o2.x = xre[c2 * PADA + t];
        o2.y = xre[(c2 + 1) * PADA + t];
        *(float2*)(out + base + (size_t)t * D_DIM + c2) = o2;
    }
}

// ---------------------------------------------------------------------------
extern "C" void kernel_launch(void* const* d_in, const int* in_sizes, int n_in,
                              void* d_out, int out_size) {
    (void)n_in; (void)out_size;
    const float* Q = (const float*)d_in[0];
    const float* K = (const float*)d_in[1];
    const float* V = (const float*)d_in[2];
    float* out = (float*)d_out;

    const int B = in_sizes[0] / (L_LEN * D_DIM);   // 16

    const int SMEM = (2 * CPA * PADA) * (int)sizeof(float);   // 33024 B
    cudaFuncSetAttribute(fused_autocorr_kernel,
                         cudaFuncAttributeMaxDynamicSharedMemorySize, SMEM);

    dim3 grid(B * 8, 512 / CPA);   // (128, 64)
    fused_autocorr_kernel<<<grid, 256, SMEM>>>(Q, K, V, out);
}